// round 16
// baseline (speedup 1.0000x reference)
#include <cuda_runtime.h>
#include <cuda_fp16.h>
#include <math.h>
#include <stdint.h>

#define BB 2
#define LL 2048
#define DD 512
#define VV 32000
#define NLAYER 4
#define PP 8
#define TOK (BB*LL)           // 4096 tokens
#define NCH 32                // scan chunks per batch
#define CHL 64                // tokens per chunk
#define NCHG (TOK/CHL)        // 64 global chunks

// ---- mma.sync GEMM geometry ----
#define HTM 128               // layer block tile M
#define HTN 128               // block tile N (all GEMMs)
#define HKC 32                // K per operand block (fp16)
#define NKC (DD/HKC)          // 16 operand blocks
#define NIT (NKC/2)           // 8 pipeline iterations (2 blocks/stage)
#define HNT (VV/HTN)          // 250  (head)
#define LNT (DD/HTN)          // 4    (layer)
#define HMT (TOK/HTM)         // 32
#define BLKB (128*HKC*2)      // 8192 bytes per (tile,kchunk) operand block
#define PADROW 40             // fp16 per padded smem row (32 data + 8 pad)
#define PRB (PADROW*2)        // 80 bytes per padded row
#define MATB (128*PRB)        // 10240 B: 128-row matrix in smem
#define STGB (4*MATB)         // layer stage: A0,B0,A1,B1 = 40960
#define NSP_L 3
#define SMEM_L (NSP_L*STGB)   // 122880
// head: TM=256
#define MATB_A2 (256*PRB)     // 20480
#define STGB2 (2*(MATB_A2 + MATB)) // 61440: A0,B0,A1,B1
#define NSP_H 2
#define SMEM_H2 (NSP_H*STGB2) // 122880
#define SMEM_SCAN (CHL*DD*4)  // 131072: fused scan+LN buffer

// ---------------- scratch (device globals: no allocation allowed) -----------
__device__ float g_h [TOK*DD];
__device__ float g_hn[TOK*DD];   // holds y2 = h + LN(h)
__device__ float g_val[TOK*DD];
__device__ float g_coef[TOK];
__device__ float g_csum[NCHG*DD];
// fp16 operands, tile-chunked layout
__device__ __align__(16) unsigned char g_Whi[(size_t)VV*DD*2];
__device__ __align__(16) unsigned char g_Ahi[(size_t)TOK*DD*2];
// layer weights: (layer, {value,out}, ntile, kc) blocks
__device__ __align__(16) unsigned char g_LWhi[(size_t)NLAYER*2*DD*DD*2];

// ---------------- helpers ----------------------------------------------------
__device__ __forceinline__ uint32_t smem_u32(const void* p) {
    uint32_t a;
    asm("{ .reg .u64 t; cvta.to.shared.u64 t, %1; cvt.u32.u64 %0, t; }"
        : "=r"(a) : "l"(p));
    return a;
}

__device__ __forceinline__ void cp16(uint32_t dst, const void* src) {
    asm volatile("cp.async.cg.shared.global [%0], [%1], 16;"
                 :: "r"(dst), "l"(src) : "memory");
}

template<int N> __device__ __forceinline__ void wait_group() {
    asm volatile("cp.async.wait_group %0;" :: "n"(N) : "memory");
}

__device__ __forceinline__ void ldsm4(uint32_t addr, uint32_t* r) {
    asm volatile("ldmatrix.sync.aligned.m8n8.x4.shared.b16 {%0,%1,%2,%3}, [%4];"
        : "=r"(r[0]), "=r"(r[1]), "=r"(r[2]), "=r"(r[3]) : "r"(addr));
}
__device__ __forceinline__ void ldsm2(uint32_t addr, uint32_t* r) {
    asm volatile("ldmatrix.sync.aligned.m8n8.x2.shared.b16 {%0,%1}, [%2];"
        : "=r"(r[0]), "=r"(r[1]) : "r"(addr));
}

#define MMA_F16(d, a, b) \
    asm volatile("mma.sync.aligned.m16n8k16.row.col.f32.f16.f16.f32 " \
        "{%0,%1,%2,%3},{%4,%5,%6,%7},{%8,%9},{%0,%1,%2,%3};" \
        : "+f"((d)[0]), "+f"((d)[1]), "+f"((d)[2]), "+f"((d)[3]) \
        : "r"((a)[0]), "r"((a)[1]), "r"((a)[2]), "r"((a)[3]), \
          "r"((b)[0]), "r"((b)[1]))

// ---------------- warp-per-token LayerNorm + fp16 split (+ coef, + gather) --
// 16 tokens per 512-thread block. Lane handles d = lane + 32*i (strided).
template<bool COEF, bool WRITEY, bool GATHER>
__global__ void __launch_bounds__(512)
k_ln(const float* __restrict__ x, const int* __restrict__ tok,
     const float* __restrict__ emb,
     const float* __restrict__ gs, const float* __restrict__ gb,
     float* __restrict__ y, unsigned char* __restrict__ ohi,
     const float* __restrict__ pW, const float* __restrict__ pb,
     const float* __restrict__ aW, const float* __restrict__ ab) {
    __shared__ float sW[COEF ? DD * 20 : 1];
    int tid = threadIdx.x, warp = tid >> 5, lane = tid & 31;
    int t = blockIdx.x * 16 + warp;

    if (COEF) {
        for (int idx = tid; idx < DD * PP; idx += 512) {
            int d = idx >> 3, p = idx & 7;
            sW[d * 20 + p]     = pW[idx];
            sW[d * 20 + 8 + p] = aW[idx];
        }
        __syncthreads();
    }

    const float* xr;
    if (GATHER) xr = emb + (size_t)tok[t] * DD + lane;
    else        xr = x + (size_t)t * DD + lane;
    float v[16];
    #pragma unroll
    for (int i = 0; i < 16; i++) v[i] = __ldg(xr + 32 * i);

    float s = 0.f;
    #pragma unroll
    for (int i = 0; i < 16; i++) s += v[i];
    #pragma unroll
    for (int o = 16; o; o >>= 1) s += __shfl_xor_sync(~0u, s, o);
    float mean = s * (1.0f / DD);

    float s2 = 0.f;
    #pragma unroll
    for (int i = 0; i < 16; i++) { float d0 = v[i] - mean; s2 += d0 * d0; }
    #pragma unroll
    for (int o = 16; o; o >>= 1) s2 += __shfl_xor_sync(~0u, s2, o);
    float rstd = rsqrtf(s2 * (1.0f / DD) + 1e-5f);

    float vn[16];
    #pragma unroll
    for (int i = 0; i < 16; i++) {
        int d = lane + 32 * i;
        vn[i] = (v[i] - mean) * rstd * __ldg(gs + d) + __ldg(gb + d);
    }
    if (WRITEY) {   // y = x + LN(x)
        float* yr = y + (size_t)t * DD + lane;
        #pragma unroll
        for (int i = 0; i < 16; i++) yr[32 * i] = v[i] + vn[i];
    }

    // fp16 round to tile-chunked layout: kc = i, ko = lane (mtile stride 128)
    {
        int mtile = t >> 7, mrow = t & 127;
        size_t base = (size_t)mtile * NKC * BLKB + mrow * 64 + lane * 2;
        #pragma unroll
        for (int i = 0; i < 16; i++)
            *(__half*)(ohi + base + (size_t)i * BLKB) = __float2half(vn[i]);
    }

    if (COEF) {
        float ap[8], aa[8];
        #pragma unroll
        for (int p = 0; p < 8; p++) { ap[p] = 0.f; aa[p] = 0.f; }
        #pragma unroll
        for (int i = 0; i < 16; i++) {
            int d = lane + 32 * i;
            float xv = vn[i];
            const float* row = &sW[d * 20];
            float4 w0 = *(const float4*)(row);
            float4 w1 = *(const float4*)(row + 4);
            float4 w2 = *(const float4*)(row + 8);
            float4 w3 = *(const float4*)(row + 12);
            ap[0] += xv * w0.x; ap[1] += xv * w0.y; ap[2] += xv * w0.z; ap[3] += xv * w0.w;
            ap[4] += xv * w1.x; ap[5] += xv * w1.y; ap[6] += xv * w1.z; ap[7] += xv * w1.w;
            aa[0] += xv * w2.x; aa[1] += xv * w2.y; aa[2] += xv * w2.z; aa[3] += xv * w2.w;
            aa[4] += xv * w3.x; aa[5] += xv * w3.y; aa[6] += xv * w3.z; aa[7] += xv * w3.w;
        }
        #pragma unroll
        for (int p = 0; p < 8; p++) {
            #pragma unroll
            for (int o = 16; o; o >>= 1) {
                ap[p] += __shfl_xor_sync(~0u, ap[p], o);
                aa[p] += __shfl_xor_sync(~0u, aa[p], o);
            }
        }
        if (lane == 0) {
            float c = 0.f;
            #pragma unroll
            for (int p = 0; p < PP; p++) {
                float ph = tanhf(ap[p] + pb[p]) * 3.14159265358979323846f;
                float av = aa[p] + ab[p];
                float sp = (av > 20.f) ? av : log1pf(expf(av));
                float sc, cc;
                sincosf(ph, &sc, &cc);
                c += (sp + 0.1f) * (cc + sc);
            }
            g_coef[t] = c;
        }
    }
}

// ---------------- fused scan + out-LN + split --------------------------------
__global__ void __launch_bounds__(512)
k_scanln(const float* __restrict__ gs, const float* __restrict__ gb,
         unsigned char* __restrict__ ohi) {
    extern __shared__ float sv[];   // [CHL][DD]
    int c = blockIdx.x;             // global chunk 0..63
    int d = threadIdx.x;            // 0..511

    float acc = 0.f;
    int c0 = c & ~(NCH - 1);        // batch start chunk
    for (int cc = c0; cc < c; cc++) acc += g_csum[(size_t)cc * DD + d];

    const float inv = 0.0220970869120796089f;  // 1/sqrt(2048)
    size_t base = (size_t)c * CHL * DD + d;
    #pragma unroll 1
    for (int l = 0; l < CHL; l += 8) {
        float v[8];
        #pragma unroll
        for (int j = 0; j < 8; j++) v[j] = g_val[base + (size_t)(l + j) * DD];
        #pragma unroll
        for (int j = 0; j < 8; j++) {
            acc += v[j];
            sv[(l + j) * DD + d] = acc * inv;
        }
    }
    __syncthreads();

    int warp = d >> 5, lane = d & 31;
    #pragma unroll 1
    for (int tt = 0; tt < 4; tt++) {
        int l = warp * 4 + tt;
        int t = c * CHL + l;
        float v[16];
        #pragma unroll
        for (int i = 0; i < 16; i++) v[i] = sv[l * DD + lane + 32 * i];

        float s = 0.f;
        #pragma unroll
        for (int i = 0; i < 16; i++) s += v[i];
        #pragma unroll
        for (int o = 16; o; o >>= 1) s += __shfl_xor_sync(~0u, s, o);
        float mean = s * (1.0f / DD);

        float s2 = 0.f;
        #pragma unroll
        for (int i = 0; i < 16; i++) { float d0 = v[i] - mean; s2 += d0 * d0; }
        #pragma unroll
        for (int o = 16; o; o >>= 1) s2 += __shfl_xor_sync(~0u, s2, o);
        float rstd = rsqrtf(s2 * (1.0f / DD) + 1e-5f);

        int mtile = t >> 7, mrow = t & 127;
        size_t b2 = (size_t)mtile * NKC * BLKB + mrow * 64 + lane * 2;
        #pragma unroll
        for (int i = 0; i < 16; i++) {
            int dd = lane + 32 * i;
            float vn = (v[i] - mean) * rstd * __ldg(gs + dd) + __ldg(gb + dd);
            *(__half*)(ohi + b2 + (size_t)i * BLKB) = __float2half(vn);
        }
    }
}

// ---------------- fp16 conversion: head W [K, VV] -> tile-chunked -----------
__global__ void k_convB(const float* __restrict__ W, int ldw,
                        unsigned char* __restrict__ dhi) {
    __shared__ float sm[32][132];
    int ntile = blockIdx.x, kc = blockIdx.y;
    int t = threadIdx.x;

    int n = t & 127, kh = t >> 7;
    #pragma unroll
    for (int j = 0; j < 16; j++) {
        int k = kh * 16 + j;
        sm[k][n] = W[(size_t)(kc * HKC + k) * ldw + ntile * HTN + n];
    }
    __syncthreads();

    int nr = t >> 1, kp = t & 1;
    __half hi[16];
    #pragma unroll
    for (int j = 0; j < 16; j++)
        hi[j] = __float2half(sm[kp * 16 + j][nr]);
    size_t blk = ((size_t)ntile * NKC + kc) * BLKB;
    uint32_t off = nr * 64 + kp * 32;
    *(uint4*)(dhi + blk + off)      = ((uint4*)hi)[0];
    *(uint4*)(dhi + blk + off + 16) = ((uint4*)hi)[1];
}

// ---------------- batched layer weight conversion (one launch) --------------
__global__ void k_convL(const float* __restrict__ vW, const float* __restrict__ oW,
                        unsigned char* __restrict__ dhi) {
    __shared__ float sm[32][132];
    int z = blockIdx.z;                 // 0..2*NLAYER-1: (layer<<1)|which
    const float* W = ((z & 1) ? oW : vW) + (size_t)(z >> 1) * DD * DD;
    unsigned char* dst = dhi + (size_t)z * DD * DD * 2;
    int ntile = blockIdx.x, kc = blockIdx.y;
    int t = threadIdx.x;

    int n = t & 127, kh = t >> 7;
    #pragma unroll
    for (int j = 0; j < 16; j++) {
        int k = kh * 16 + j;
        sm[k][n] = W[(size_t)(kc * HKC + k) * DD + ntile * HTN + n];
    }
    __syncthreads();

    int nr = t >> 1, kp = t & 1;
    __half hi[16];
    #pragma unroll
    for (int j = 0; j < 16; j++)
        hi[j] = __float2half(sm[kp * 16 + j][nr]);
    size_t blk = ((size_t)ntile * NKC + kc) * BLKB;
    uint32_t off = nr * 64 + kp * 32;
    *(uint4*)(dst + blk + off)      = ((uint4*)hi)[0];
    *(uint4*)(dst + blk + off + 16) = ((uint4*)hi)[1];
}

// ---------------- layer GEMM: 128x128, 512 thr, double-kc 3-stage ------------
// 16 warps in a 4x4 grid, each 32x32. CSUM: per-64-row chunk column sums.
template<bool CSUM>
__global__ void __launch_bounds__(512)
k_mm(const unsigned char* __restrict__ A_b, const unsigned char* __restrict__ B_b,
     const float* __restrict__ bias, const float* __restrict__ rowscale,
     const float* __restrict__ add0,
     float* __restrict__ C, int ldc) {
    extern __shared__ __align__(16) unsigned char smx[];
    __shared__ float s_cs[4][128];

    int tid = threadIdx.x, wid = tid >> 5, lane = tid & 31;
    int mtile = blockIdx.x, ntile = blockIdx.y;

    const unsigned char* srcA = A_b + (size_t)mtile * NKC * BLKB;
    const unsigned char* srcB = B_b + (size_t)ntile * NKC * BLKB;

    uint32_t smbase = smem_u32(smx);

    // stage layout: [A(kc0)][B(kc0)][A(kc1)][B(kc1)], each MATB
    auto copy_stage = [&](int s, int it) {
        uint32_t dst0 = smbase + s * STGB;
        int q = tid;                    // 512 quads of 16B per matrix
        int row = q >> 2, c = q & 3;
        uint32_t doff = row * PRB + c * 16;
        size_t so0 = (size_t)(2 * it) * BLKB + (size_t)q * 16;
        size_t so1 = so0 + BLKB;
        cp16(dst0 + doff,            srcA + so0);
        cp16(dst0 + MATB + doff,     srcB + so0);
        cp16(dst0 + 2 * MATB + doff, srcA + so1);
        cp16(dst0 + 3 * MATB + doff, srcB + so1);
        asm volatile("cp.async.commit_group;" ::: "memory");
    };

    float acc[2][4][4];
    #pragma unroll
    for (int i = 0; i < 2; i++)
        #pragma unroll
        for (int j = 0; j < 4; j++)
            #pragma unroll
            for (int q = 0; q < 4; q++) acc[i][j][q] = 0.f;

    int wm = (wid >> 2) * 32, wn = (wid & 3) * 32;
    uint32_t aoff = (uint32_t)(wm + (lane & 15)) * PRB + ((lane >> 4) << 4);
    uint32_t boff = (uint32_t)(wn + (lane & 7)) * PRB + ((lane & 8) << 1);

    #pragma unroll
    for (int s = 0; s < NSP_L - 1; s++) copy_stage(s, s);

    for (int it = 0; it < NIT; it++) {
        wait_group<NSP_L - 2>();
        __syncthreads();
        int pf = it + NSP_L - 1;
        if (pf < NIT) copy_stage(pf % NSP_L, pf);
        else asm volatile("cp.async.commit_group;" ::: "memory");

        uint32_t st0 = smbase + (it % NSP_L) * STGB;
        #pragma unroll
        for (int half = 0; half < 2; half++) {
            uint32_t aA = st0 + half * (2 * MATB) + aoff;
            uint32_t aB = st0 + half * (2 * MATB) + MATB + boff;
            #pragma unroll
            for (int kk = 0; kk < 2; kk++) {
                uint32_t kb = kk * 32;          // 16 fp16 = 32 bytes
                uint32_t ah[2][4], bh[4][2];
                #pragma unroll
                for (int fm = 0; fm < 2; fm++)
                    ldsm4(aA + fm * (16 * PRB) + kb, ah[fm]);
                #pragma unroll
                for (int fn = 0; fn < 4; fn++)
                    ldsm2(aB + fn * (8 * PRB) + kb, bh[fn]);
                #pragma unroll
                for (int fm = 0; fm < 2; fm++)
                    #pragma unroll
                    for (int fn = 0; fn < 4; fn++)
                        MMA_F16(acc[fm][fn], ah[fm], bh[fn]);
            }
        }
    }
    __syncthreads();

    // --- epilogue -----------------------------------------------------------
    int g = lane >> 2, tig = lane & 3;
    int orow0 = mtile * HTM + wm + g;
    int ocol0 = ntile * HTN + wn + tig * 2;
    float cs[4][2];
    if (CSUM) {
        #pragma unroll
        for (int fn = 0; fn < 4; fn++) { cs[fn][0] = 0.f; cs[fn][1] = 0.f; }
    }
    #pragma unroll
    for (int fn = 0; fn < 4; fn++) {
        int c = ocol0 + fn * 8;
        float b0 = bias[c], b1 = bias[c + 1];
        #pragma unroll
        for (int fm = 0; fm < 2; fm++) {
            int r = orow0 + fm * 16;
            size_t i0 = (size_t)r * ldc + c;
            size_t i1 = (size_t)(r + 8) * ldc + c;
            float v00 = acc[fm][fn][0] + b0, v01 = acc[fm][fn][1] + b1;
            float v10 = acc[fm][fn][2] + b0, v11 = acc[fm][fn][3] + b1;
            if (rowscale) {
                float r0 = rowscale[r], r1 = rowscale[r + 8];
                v00 *= r0; v01 *= r0; v10 *= r1; v11 *= r1;
            }
            if (add0) {
                float2 a0 = *(const float2*)(add0 + i0);
                float2 a1 = *(const float2*)(add0 + i1);
                v00 += a0.x; v01 += a0.y; v10 += a1.x; v11 += a1.y;
            }
            if (CSUM) {
                cs[fn][0] += v00 + v10;
                cs[fn][1] += v01 + v11;
            }
            *(float2*)(C + i0) = make_float2(v00, v01);
            *(float2*)(C + i1) = make_float2(v10, v11);
        }
    }
    if (CSUM) {
        #pragma unroll
        for (int fn = 0; fn < 4; fn++)
            #pragma unroll
            for (int j = 0; j < 2; j++)
                #pragma unroll
                for (int o = 16; o >= 4; o >>= 1)
                    cs[fn][j] += __shfl_xor_sync(~0u, cs[fn][j], o);
        int mgrp = wid >> 2;     // 0..3, each covers 32 rows
        if (g == 0) {
            #pragma unroll
            for (int fn = 0; fn < 4; fn++) {
                s_cs[mgrp][wn + fn * 8 + tig * 2]     = cs[fn][0];
                s_cs[mgrp][wn + fn * 8 + tig * 2 + 1] = cs[fn][1];
            }
        }
        __syncthreads();
        if (tid < 128) {
            g_csum[(size_t)(mtile * 2 + 0) * DD + ntile * 128 + tid] =
                s_cs[0][tid] + s_cs[1][tid];
            g_csum[(size_t)(mtile * 2 + 1) * DD + ntile * 128 + tid] =
                s_cs[2][tid] + s_cs[3][tid];
        }
    }
}

// ---------------- head GEMM: 256x128, 512 thr, double-kc 2-stage -------------
__global__ void __launch_bounds__(512, 1)
k_head(const unsigned char* __restrict__ A_b, const unsigned char* __restrict__ B_b,
       const float* __restrict__ bias, float* __restrict__ C) {
    extern __shared__ __align__(16) unsigned char smx[];

    int tid = threadIdx.x, wid = tid >> 5, lane = tid & 31;
    int mtile = blockIdx.x, ntile = blockIdx.y;

    const unsigned char* srcA = A_b + (size_t)(2 * mtile) * NKC * BLKB;
    const unsigned char* srcB = B_b + (size_t)ntile * NKC * BLKB;
    uint32_t smbase = smem_u32(smx);

    // stage layout: [A(kc0) MATB_A2][B(kc0) MATB][A(kc1) MATB_A2][B(kc1) MATB]
    auto copy_half = [&](uint32_t dst0, int kc) {
        #pragma unroll
        for (int i = 0; i < 2; i++) {
            int q = i * 512 + tid;
            int row = q >> 2, c = q & 3;
            size_t soff = (size_t)(row >> 7) * NKC * BLKB + (size_t)kc * BLKB
                        + (size_t)(row & 127) * 64 + c * 16;
            cp16(dst0 + row * PRB + c * 16, srcA + soff);
        }
        {
            int q = tid;
            int row = q >> 2, c = q & 3;
            cp16(dst0 + MATB_A2 + row * PRB + c * 16,
                 srcB + (size_t)kc * BLKB + (size_t)q * 16);
        }
    };
    auto copy_stage = [&](int s, int it) {
        uint32_t dst0 = smbase + s * STGB2;
        copy_half(dst0, 2 * it);
        copy_half(dst0 + MATB_A2 + MATB, 2 * it + 1);
        asm volatile("cp.async.commit_group;" ::: "memory");
    };

    float acc[4][4][4];
    #pragma unroll
    for (int i = 0; i < 4; i++)
        #pragma unroll
        for (int j = 0; j < 4; j++)
            #pragma unroll
            for (int q = 0; q < 4; q++) acc[i][j][q] = 0.f;

    int wm = (wid >> 2) * 64, wn = (wid & 3) * 32;   // 4x4 warp grid, 64x32 each
    uint32_t aoff = (uint32_t)(wm + (lane & 15)) * PRB + ((lane >> 4) << 4);
    uint32_t boff = (uint32_t)(wn + (lane & 7)) * PRB + ((lane & 8) << 1);

    copy_stage(0, 0);

    for (int it = 0; it < NIT; it++) {
        wait_group<0>();
        __syncthreads();
        int pf = it + 1;
        if (pf < NIT) copy_stage(pf % NSP_H, pf);
        else asm volatile("cp.async.commit_group;" ::: "memory");

        uint32_t st0 = smbase + (it % NSP_H) * STGB2;
        #pragma unroll
        for (int half = 0; half < 2; half++) {
            uint32_t aA = st0 + half * (MATB_A2 + MATB) + aoff;
            uint32_t aB = st0 + half * (MATB_A2 + MATB) + MATB_A2 + boff;
            #pragma unroll
            for (int kk = 0; kk < 2; kk++) {
                uint32_t kb = kk * 32;
                uint32_t ah[4][4], bh[4][2];
                #pragma unroll
                for (int fm = 0; fm < 4; fm++)
                    ldsm4(aA + fm * (16 * PRB) + kb, ah[fm]);
                #pragma unroll
                for (int fn = 0; fn < 4; fn++)
                    ldsm2(aB + fn * (8 * PRB) + kb, bh[fn]);
                #pragma unroll
                for (int fm = 0; fm < 4; fm++)
                    #pragma unroll
                    for (int fn = 0; fn < 4; fn++)
                        MMA_F16(acc[fm][fn], ah[fm], bh[fn]);
            }
        }
    }

    // --- epilogue -----------------------------------------------------------
    int g = lane >> 2, tig = lane & 3;
    int orow0 = mtile * 256 + wm + g;
    int ocol0 = ntile * HTN + wn + tig * 2;
    #pragma unroll
    for (int fn = 0; fn < 4; fn++) {
        int c = ocol0 + fn * 8;
        float b0 = bias[c], b1 = bias[c + 1];
        #pragma unroll
        for (int fm = 0; fm < 4; fm++) {
            int r = orow0 + fm * 16;
            *(float2*)(C + (size_t)r * VV + c) =
                make_float2(acc[fm][fn][0] + b0, acc[fm][fn][1] + b1);
            *(float2*)(C + (size_t)(r + 8) * VV + c) =
                make_float2(acc[fm][fn][2] + b0, acc[fm][fn][3] + b1);
        }
    }
}

// ---------------- launch ----------------------------------------------------
extern "C" void kernel_launch(void* const* d_in, const int* in_sizes, int n_in,
                              void* d_out, int out_size) {
    const int*   tokens        = (const int*)  d_in[0];
    const float* embed         = (const float*)d_in[1];
    const float* ln_scale      = (const float*)d_in[2];
    const float* ln_bias       = (const float*)d_in[3];
    const float* phase_W       = (const float*)d_in[4];
    const float* phase_b       = (const float*)d_in[5];
    const float* amp_W         = (const float*)d_in[6];
    const float* amp_b         = (const float*)d_in[7];
    const float* value_W       = (const float*)d_in[8];
    const float* value_b       = (const float*)d_in[9];
    const float* out_ln_scale  = (const float*)d_in[10];
    const float* out_ln_bias   = (const float*)d_in[11];
    const float* out_W         = (const float*)d_in[12];
    const float* out_b         = (const float*)d_in[13];
    const float* normout_scale = (const float*)d_in[14];
    const float* normout_bias  = (const float*)d_in[15];
    const float* head_W        = (const float*)d_in[16];
    const float* head_b        = (const float*)d_in[17];
    float* out = (float*)d_out;

    float *h, *hn, *val, *coef;
    unsigned char *whi, *ahi, *lwhi;
    cudaGetSymbolAddress((void**)&h,    g_h);
    cudaGetSymbolAddress((void**)&hn,   g_hn);
    cudaGetSymbolAddress((void**)&val,  g_val);
    cudaGetSymbolAddress((void**)&coef, g_coef);
    cudaGetSymbolAddress((void**)&whi,  g_Whi);
    cudaGetSymbolAddress((void**)&ahi,  g_Ahi);
    cudaGetSymbolAddress((void**)&lwhi, g_LWhi);

    cudaFuncSetAttribute(k_mm<true >, cudaFuncAttributeMaxDynamicSharedMemorySize, SMEM_L);
    cudaFuncSetAttribute(k_mm<false>, cudaFuncAttributeMaxDynamicSharedMemorySize, SMEM_L);
    cudaFuncSetAttribute(k_head,      cudaFuncAttributeMaxDynamicSharedMemorySize, SMEM_H2);
    cudaFuncSetAttribute(k_scanln,    cudaFuncAttributeMaxDynamicSharedMemorySize, SMEM_SCAN);

    k_convB<<<dim3(HNT, NKC), 256>>>(head_W, VV, whi);
    k_convL<<<dim3(LNT, NKC, 2 * NLAYER), 256>>>(value_W, out_W, lwhi);

    dim3 mmLayer(HMT, LNT);
    size_t lwstep = (size_t)DD * DD * 2;

    for (int i = 0; i < NLAYER; i++) {
        // y2 = h + LN(h) into hn; split operand; fused coef.
        if (i == 0)
            k_ln<true, true, true><<<TOK / 16, 512>>>(
                nullptr, tokens, embed, ln_scale, ln_bias, hn, ahi,
                phase_W, phase_b, amp_W, amp_b);
        else
            k_ln<true, true, false><<<TOK / 16, 512>>>(
                h, nullptr, nullptr, ln_scale + i * DD, ln_bias + i * DD, hn, ahi,
                phase_W + (size_t)i * DD * PP, phase_b + i * PP,
                amp_W + (size_t)i * DD * PP, amp_b + i * PP);
        // val = (hn @ vW + vb) * coef, 64-token chunk sums fused
        k_mm<true><<<mmLayer, 512, SMEM_L>>>(
            ahi, lwhi + (2*i+0)*lwstep,
            value_b + i * DD, coef, nullptr, val, DD);
        // fused scan + out-LN + split operand
        k_scanln<<<NCHG, 512, SMEM_SCAN>>>(
            out_ln_scale + i * DD, out_ln_bias + i * DD, ahi);
        // h = y2 + sn @ oW + ob
        k_mm<false><<<mmLayer, 512, SMEM_L>>>(
            ahi, lwhi + (2*i+1)*lwstep,
            out_b + i * DD, nullptr, hn, h, DD);
    }

    // final: split(LN(h)); head GEMM with 256-row tiles
    k_ln<false, false, false><<<TOK / 16, 512>>>(
        h, nullptr, nullptr, normout_scale, normout_bias,
        nullptr, ahi, nullptr, nullptr, nullptr, nullptr);
    k_head<<<dim3(TOK / 256, HNT), 512, SMEM_H2>>>(ahi, whi, head_b, out);
}

// round 17
// speedup vs baseline: 1.1490x; 1.1490x over previous
#include <cuda_runtime.h>
#include <cuda_fp16.h>
#include <math.h>
#include <stdint.h>

#define BB 2
#define LL 2048
#define DD 512
#define VV 32000
#define NLAYER 4
#define PP 8
#define TOK (BB*LL)           // 4096 tokens
#define NCH 32                // scan chunks per batch
#define CHL 64                // tokens per chunk
#define NCHG (TOK/CHL)        // 64 global chunks

// ---- mma.sync GEMM geometry ----
#define HTM 128               // layer block tile M
#define HTN 128               // block tile N (all GEMMs)
#define HKC 32                // K per pipeline chunk (fp16)
#define NKC (DD/HKC)          // 16
#define HNT (VV/HTN)          // 250  (head)
#define LNT (DD/HTN)          // 4    (layer)
#define HMT (TOK/HTM)         // 32
#define BLKB (128*HKC*2)      // 8192 bytes per (tile,kchunk) operand block
#define PADROW 40             // fp16 per padded smem row (32 data + 8 pad)
#define PRB (PADROW*2)        // 80 bytes per padded row
#define MATB (128*PRB)        // 10240 B: 128-row matrix in smem
#define STGB (2*MATB)         // layer stage (A, B)
#define NSP_L 4
#define SMEM_L (NSP_L*STGB)   // 81920: layer GEMMs, 4-stage
// head: TM=256
#define MATB_A2 (256*PRB)     // 20480
#define STGB2 (MATB_A2 + MATB) // 30720
#define NSP_H 3
#define SMEM_H2 (NSP_H*STGB2) // 92160: head, 3-stage
#define SMEM_SCAN (CHL*DD*4)  // 131072: fused scan+LN buffer

// ---------------- scratch (device globals: no allocation allowed) -----------
__device__ float g_h [TOK*DD];
__device__ float g_hn[TOK*DD];   // holds y2 = h + LN(h)
__device__ float g_val[TOK*DD];
__device__ float g_coef[TOK];
__device__ float g_csum[NCHG*DD];
// fp16 operands, tile-chunked layout
__device__ __align__(16) unsigned char g_Whi[(size_t)VV*DD*2];
__device__ __align__(16) unsigned char g_Ahi[(size_t)TOK*DD*2];
// layer weights: (layer, {value,out}, ntile, kc) blocks
__device__ __align__(16) unsigned char g_LWhi[(size_t)NLAYER*2*DD*DD*2];

// ---------------- helpers ----------------------------------------------------
__device__ __forceinline__ uint32_t smem_u32(const void* p) {
    uint32_t a;
    asm("{ .reg .u64 t; cvta.to.shared.u64 t, %1; cvt.u32.u64 %0, t; }"
        : "=r"(a) : "l"(p));
    return a;
}

__device__ __forceinline__ void cp16(uint32_t dst, const void* src) {
    asm volatile("cp.async.cg.shared.global [%0], [%1], 16;"
                 :: "r"(dst), "l"(src) : "memory");
}

template<int N> __device__ __forceinline__ void wait_group() {
    asm volatile("cp.async.wait_group %0;" :: "n"(N) : "memory");
}

__device__ __forceinline__ void ldsm4(uint32_t addr, uint32_t* r) {
    asm volatile("ldmatrix.sync.aligned.m8n8.x4.shared.b16 {%0,%1,%2,%3}, [%4];"
        : "=r"(r[0]), "=r"(r[1]), "=r"(r[2]), "=r"(r[3]) : "r"(addr));
}
__device__ __forceinline__ void ldsm2(uint32_t addr, uint32_t* r) {
    asm volatile("ldmatrix.sync.aligned.m8n8.x2.shared.b16 {%0,%1}, [%2];"
        : "=r"(r[0]), "=r"(r[1]) : "r"(addr));
}

#define MMA_F16(d, a, b) \
    asm volatile("mma.sync.aligned.m16n8k16.row.col.f32.f16.f16.f32 " \
        "{%0,%1,%2,%3},{%4,%5,%6,%7},{%8,%9},{%0,%1,%2,%3};" \
        : "+f"((d)[0]), "+f"((d)[1]), "+f"((d)[2]), "+f"((d)[3]) \
        : "r"((a)[0]), "r"((a)[1]), "r"((a)[2]), "r"((a)[3]), \
          "r"((b)[0]), "r"((b)[1]))

// ---------------- warp-per-token LayerNorm + fp16 split (+ coef, + gather) --
// 16 tokens per 512-thread block. Lane handles d = lane + 32*i (strided).
template<bool COEF, bool WRITEY, bool GATHER>
__global__ void __launch_bounds__(512)
k_ln(const float* __restrict__ x, const int* __restrict__ tok,
     const float* __restrict__ emb,
     const float* __restrict__ gs, const float* __restrict__ gb,
     float* __restrict__ y, unsigned char* __restrict__ ohi,
     const float* __restrict__ pW, const float* __restrict__ pb,
     const float* __restrict__ aW, const float* __restrict__ ab) {
    __shared__ float sW[COEF ? DD * 20 : 1];
    int tid = threadIdx.x, warp = tid >> 5, lane = tid & 31;
    int t = blockIdx.x * 16 + warp;

    if (COEF) {
        for (int idx = tid; idx < DD * PP; idx += 512) {
            int d = idx >> 3, p = idx & 7;
            sW[d * 20 + p]     = pW[idx];
            sW[d * 20 + 8 + p] = aW[idx];
        }
        __syncthreads();
    }

    const float* xr;
    if (GATHER) xr = emb + (size_t)tok[t] * DD + lane;
    else        xr = x + (size_t)t * DD + lane;
    float v[16];
    #pragma unroll
    for (int i = 0; i < 16; i++) v[i] = __ldg(xr + 32 * i);

    float s = 0.f;
    #pragma unroll
    for (int i = 0; i < 16; i++) s += v[i];
    #pragma unroll
    for (int o = 16; o; o >>= 1) s += __shfl_xor_sync(~0u, s, o);
    float mean = s * (1.0f / DD);

    float s2 = 0.f;
    #pragma unroll
    for (int i = 0; i < 16; i++) { float d0 = v[i] - mean; s2 += d0 * d0; }
    #pragma unroll
    for (int o = 16; o; o >>= 1) s2 += __shfl_xor_sync(~0u, s2, o);
    float rstd = rsqrtf(s2 * (1.0f / DD) + 1e-5f);

    float vn[16];
    #pragma unroll
    for (int i = 0; i < 16; i++) {
        int d = lane + 32 * i;
        vn[i] = (v[i] - mean) * rstd * __ldg(gs + d) + __ldg(gb + d);
    }
    if (WRITEY) {   // y = x + LN(x)
        float* yr = y + (size_t)t * DD + lane;
        #pragma unroll
        for (int i = 0; i < 16; i++) yr[32 * i] = v[i] + vn[i];
    }

    // fp16 round to tile-chunked layout: kc = i, ko = lane (mtile stride 128)
    {
        int mtile = t >> 7, mrow = t & 127;
        size_t base = (size_t)mtile * NKC * BLKB + mrow * 64 + lane * 2;
        #pragma unroll
        for (int i = 0; i < 16; i++)
            *(__half*)(ohi + base + (size_t)i * BLKB) = __float2half(vn[i]);
    }

    if (COEF) {
        float ap[8], aa[8];
        #pragma unroll
        for (int p = 0; p < 8; p++) { ap[p] = 0.f; aa[p] = 0.f; }
        #pragma unroll
        for (int i = 0; i < 16; i++) {
            int d = lane + 32 * i;
            float xv = vn[i];
            const float* row = &sW[d * 20];
            float4 w0 = *(const float4*)(row);
            float4 w1 = *(const float4*)(row + 4);
            float4 w2 = *(const float4*)(row + 8);
            float4 w3 = *(const float4*)(row + 12);
            ap[0] += xv * w0.x; ap[1] += xv * w0.y; ap[2] += xv * w0.z; ap[3] += xv * w0.w;
            ap[4] += xv * w1.x; ap[5] += xv * w1.y; ap[6] += xv * w1.z; ap[7] += xv * w1.w;
            aa[0] += xv * w2.x; aa[1] += xv * w2.y; aa[2] += xv * w2.z; aa[3] += xv * w2.w;
            aa[4] += xv * w3.x; aa[5] += xv * w3.y; aa[6] += xv * w3.z; aa[7] += xv * w3.w;
        }
        #pragma unroll
        for (int p = 0; p < 8; p++) {
            #pragma unroll
            for (int o = 16; o; o >>= 1) {
                ap[p] += __shfl_xor_sync(~0u, ap[p], o);
                aa[p] += __shfl_xor_sync(~0u, aa[p], o);
            }
        }
        if (lane == 0) {
            float c = 0.f;
            #pragma unroll
            for (int p = 0; p < PP; p++) {
                float ph = tanhf(ap[p] + pb[p]) * 3.14159265358979323846f;
                float av = aa[p] + ab[p];
                float sp = (av > 20.f) ? av : log1pf(expf(av));
                float sc, cc;
                sincosf(ph, &sc, &cc);
                c += (sp + 0.1f) * (cc + sc);
            }
            g_coef[t] = c;
        }
    }
}

// ---------------- fused scan + out-LN + split --------------------------------
__global__ void __launch_bounds__(512)
k_scanln(const float* __restrict__ gs, const float* __restrict__ gb,
         unsigned char* __restrict__ ohi) {
    extern __shared__ float sv[];   // [CHL][DD]
    int c = blockIdx.x;             // global chunk 0..63
    int d = threadIdx.x;            // 0..511

    float acc = 0.f;
    int c0 = c & ~(NCH - 1);        // batch start chunk
    for (int cc = c0; cc < c; cc++) acc += g_csum[(size_t)cc * DD + d];

    const float inv = 0.0220970869120796089f;  // 1/sqrt(2048)
    size_t base = (size_t)c * CHL * DD + d;
    #pragma unroll 1
    for (int l = 0; l < CHL; l += 8) {
        float v[8];
        #pragma unroll
        for (int j = 0; j < 8; j++) v[j] = g_val[base + (size_t)(l + j) * DD];
        #pragma unroll
        for (int j = 0; j < 8; j++) {
            acc += v[j];
            sv[(l + j) * DD + d] = acc * inv;
        }
    }
    __syncthreads();

    int warp = d >> 5, lane = d & 31;
    #pragma unroll 1
    for (int tt = 0; tt < 4; tt++) {
        int l = warp * 4 + tt;
        int t = c * CHL + l;
        float v[16];
        #pragma unroll
        for (int i = 0; i < 16; i++) v[i] = sv[l * DD + lane + 32 * i];

        float s = 0.f;
        #pragma unroll
        for (int i = 0; i < 16; i++) s += v[i];
        #pragma unroll
        for (int o = 16; o; o >>= 1) s += __shfl_xor_sync(~0u, s, o);
        float mean = s * (1.0f / DD);

        float s2 = 0.f;
        #pragma unroll
        for (int i = 0; i < 16; i++) { float d0 = v[i] - mean; s2 += d0 * d0; }
        #pragma unroll
        for (int o = 16; o; o >>= 1) s2 += __shfl_xor_sync(~0u, s2, o);
        float rstd = rsqrtf(s2 * (1.0f / DD) + 1e-5f);

        int mtile = t >> 7, mrow = t & 127;
        size_t b2 = (size_t)mtile * NKC * BLKB + mrow * 64 + lane * 2;
        #pragma unroll
        for (int i = 0; i < 16; i++) {
            int dd = lane + 32 * i;
            float vn = (v[i] - mean) * rstd * __ldg(gs + dd) + __ldg(gb + dd);
            *(__half*)(ohi + b2 + (size_t)i * BLKB) = __float2half(vn);
        }
    }
}

// ---------------- fp16 conversion: head W [K, VV] -> tile-chunked -----------
__global__ void k_convB(const float* __restrict__ W, int ldw,
                        unsigned char* __restrict__ dhi) {
    __shared__ float sm[32][132];
    int ntile = blockIdx.x, kc = blockIdx.y;
    int t = threadIdx.x;

    int n = t & 127, kh = t >> 7;
    #pragma unroll
    for (int j = 0; j < 16; j++) {
        int k = kh * 16 + j;
        sm[k][n] = W[(size_t)(kc * HKC + k) * ldw + ntile * HTN + n];
    }
    __syncthreads();

    int nr = t >> 1, kp = t & 1;
    __half hi[16];
    #pragma unroll
    for (int j = 0; j < 16; j++)
        hi[j] = __float2half(sm[kp * 16 + j][nr]);
    size_t blk = ((size_t)ntile * NKC + kc) * BLKB;
    uint32_t off = nr * 64 + kp * 32;
    *(uint4*)(dhi + blk + off)      = ((uint4*)hi)[0];
    *(uint4*)(dhi + blk + off + 16) = ((uint4*)hi)[1];
}

// ---------------- batched layer weight conversion (one launch) --------------
__global__ void k_convL(const float* __restrict__ vW, const float* __restrict__ oW,
                        unsigned char* __restrict__ dhi) {
    __shared__ float sm[32][132];
    int z = blockIdx.z;                 // 0..2*NLAYER-1: (layer<<1)|which
    const float* W = ((z & 1) ? oW : vW) + (size_t)(z >> 1) * DD * DD;
    unsigned char* dst = dhi + (size_t)z * DD * DD * 2;
    int ntile = blockIdx.x, kc = blockIdx.y;
    int t = threadIdx.x;

    int n = t & 127, kh = t >> 7;
    #pragma unroll
    for (int j = 0; j < 16; j++) {
        int k = kh * 16 + j;
        sm[k][n] = W[(size_t)(kc * HKC + k) * DD + ntile * HTN + n];
    }
    __syncthreads();

    int nr = t >> 1, kp = t & 1;
    __half hi[16];
    #pragma unroll
    for (int j = 0; j < 16; j++)
        hi[j] = __float2half(sm[kp * 16 + j][nr]);
    size_t blk = ((size_t)ntile * NKC + kc) * BLKB;
    uint32_t off = nr * 64 + kp * 32;
    *(uint4*)(dst + blk + off)      = ((uint4*)hi)[0];
    *(uint4*)(dst + blk + off + 16) = ((uint4*)hi)[1];
}

// ---------------- layer GEMM: 128x128 tile, 512 thr, single-sync 4-stage -----
// 16 warps in a 4x4 grid, each 32x32. CSUM: per-64-row chunk column sums.
template<bool CSUM>
__global__ void __launch_bounds__(512)
k_mm(const unsigned char* __restrict__ A_b, const unsigned char* __restrict__ B_b,
     const float* __restrict__ bias, const float* __restrict__ rowscale,
     const float* __restrict__ add0,
     float* __restrict__ C, int ldc) {
    extern __shared__ __align__(16) unsigned char smx[];
    __shared__ float s_cs[4][128];

    int tid = threadIdx.x, wid = tid >> 5, lane = tid & 31;
    int mtile = blockIdx.x, ntile = blockIdx.y;

    const unsigned char* srcA = A_b + (size_t)mtile * NKC * BLKB;
    const unsigned char* srcB = B_b + (size_t)ntile * NKC * BLKB;

    uint32_t smbase = smem_u32(smx);

    auto copy_stage = [&](int s, int kc) {
        uint32_t dst0 = smbase + s * STGB;
        int q = tid;                    // 512 quads of 16B per matrix
        int row = q >> 2, c = q & 3;
        uint32_t doff = row * PRB + c * 16;
        cp16(dst0 + doff,        srcA + (size_t)kc * BLKB + (size_t)q * 16);
        cp16(dst0 + MATB + doff, srcB + (size_t)kc * BLKB + (size_t)q * 16);
        asm volatile("cp.async.commit_group;" ::: "memory");
    };

    float acc[2][4][4];
    #pragma unroll
    for (int i = 0; i < 2; i++)
        #pragma unroll
        for (int j = 0; j < 4; j++)
            #pragma unroll
            for (int q = 0; q < 4; q++) acc[i][j][q] = 0.f;

    int wm = (wid >> 2) * 32, wn = (wid & 3) * 32;
    uint32_t aoff = (uint32_t)(wm + (lane & 15)) * PRB + ((lane >> 4) << 4);
    uint32_t boff = (uint32_t)(wn + (lane & 7)) * PRB + ((lane & 8) << 1);

    // single-sync pipeline: prologue fills NSP_L-1 stages
    #pragma unroll
    for (int s = 0; s < NSP_L - 1; s++) copy_stage(s, s);

    for (int kc = 0; kc < NKC; kc++) {
        wait_group<NSP_L - 2>();
        __syncthreads();
        // prefetch kc+NSP_L-1 into slot (kc-1)%NSP_L — all warps past iter kc-1
        int pf = kc + NSP_L - 1;
        if (pf < NKC) copy_stage(pf % NSP_L, pf);
        else asm volatile("cp.async.commit_group;" ::: "memory");

        uint32_t stA = smbase + (kc % NSP_L) * STGB;
        uint32_t aA = stA + aoff;
        uint32_t aB = stA + MATB + boff;

        #pragma unroll
        for (int kk = 0; kk < 2; kk++) {
            uint32_t kb = kk * 32;          // 16 fp16 = 32 bytes
            uint32_t ah[2][4], bh[4][2];
            #pragma unroll
            for (int fm = 0; fm < 2; fm++)
                ldsm4(aA + fm * (16 * PRB) + kb, ah[fm]);
            #pragma unroll
            for (int fn = 0; fn < 4; fn++)
                ldsm2(aB + fn * (8 * PRB) + kb, bh[fn]);
            #pragma unroll
            for (int fm = 0; fm < 2; fm++)
                #pragma unroll
                for (int fn = 0; fn < 4; fn++)
                    MMA_F16(acc[fm][fn], ah[fm], bh[fn]);
        }
    }
    __syncthreads();

    // --- epilogue -----------------------------------------------------------
    int g = lane >> 2, tig = lane & 3;
    int orow0 = mtile * HTM + wm + g;
    int ocol0 = ntile * HTN + wn + tig * 2;
    float cs[4][2];
    if (CSUM) {
        #pragma unroll
        for (int fn = 0; fn < 4; fn++) { cs[fn][0] = 0.f; cs[fn][1] = 0.f; }
    }
    #pragma unroll
    for (int fn = 0; fn < 4; fn++) {
        int c = ocol0 + fn * 8;
        float b0 = bias[c], b1 = bias[c + 1];
        #pragma unroll
        for (int fm = 0; fm < 2; fm++) {
            int r = orow0 + fm * 16;
            size_t i0 = (size_t)r * ldc + c;
            size_t i1 = (size_t)(r + 8) * ldc + c;
            float v00 = acc[fm][fn][0] + b0, v01 = acc[fm][fn][1] + b1;
            float v10 = acc[fm][fn][2] + b0, v11 = acc[fm][fn][3] + b1;
            if (rowscale) {
                float r0 = rowscale[r], r1 = rowscale[r + 8];
                v00 *= r0; v01 *= r0; v10 *= r1; v11 *= r1;
            }
            if (add0) {
                float2 a0 = *(const float2*)(add0 + i0);
                float2 a1 = *(const float2*)(add0 + i1);
                v00 += a0.x; v01 += a0.y; v10 += a1.x; v11 += a1.y;
            }
            if (CSUM) {
                cs[fn][0] += v00 + v10;
                cs[fn][1] += v01 + v11;
            }
            *(float2*)(C + i0) = make_float2(v00, v01);
            *(float2*)(C + i1) = make_float2(v10, v11);
        }
    }
    if (CSUM) {
        #pragma unroll
        for (int fn = 0; fn < 4; fn++)
            #pragma unroll
            for (int j = 0; j < 2; j++)
                #pragma unroll
                for (int o = 16; o >= 4; o >>= 1)
                    cs[fn][j] += __shfl_xor_sync(~0u, cs[fn][j], o);
        int mgrp = wid >> 2;     // 0..3, each covers 32 rows
        if (g == 0) {
            #pragma unroll
            for (int fn = 0; fn < 4; fn++) {
                s_cs[mgrp][wn + fn * 8 + tig * 2]     = cs[fn][0];
                s_cs[mgrp][wn + fn * 8 + tig * 2 + 1] = cs[fn][1];
            }
        }
        __syncthreads();
        if (tid < 128) {
            g_csum[(size_t)(mtile * 2 + 0) * DD + ntile * 128 + tid] =
                s_cs[0][tid] + s_cs[1][tid];
            g_csum[(size_t)(mtile * 2 + 1) * DD + ntile * 128 + tid] =
                s_cs[2][tid] + s_cs[3][tid];
        }
    }
}

// ---------------- head GEMM: 256x128 tile, 512 thr, single-sync 3-stage ------
__global__ void __launch_bounds__(512, 1)
k_head(const unsigned char* __restrict__ A_b, const unsigned char* __restrict__ B_b,
       const float* __restrict__ bias, float* __restrict__ C) {
    extern __shared__ __align__(16) unsigned char smx[];

    int tid = threadIdx.x, wid = tid >> 5, lane = tid & 31;
    int mtile = blockIdx.x, ntile = blockIdx.y;

    const unsigned char* srcA = A_b + (size_t)(2 * mtile) * NKC * BLKB;
    const unsigned char* srcB = B_b + (size_t)ntile * NKC * BLKB;
    uint32_t smbase = smem_u32(smx);

    auto copy_stage = [&](int s, int kc) {
        uint32_t dst0 = smbase + s * STGB2;
        #pragma unroll
        for (int i = 0; i < 2; i++) {
            int q = i * 512 + tid;
            int row = q >> 2, c = q & 3;
            size_t soff = (size_t)(row >> 7) * NKC * BLKB + (size_t)kc * BLKB
                        + (size_t)(row & 127) * 64 + c * 16;
            cp16(dst0 + row * PRB + c * 16, srcA + soff);
        }
        {
            int q = tid;
            int row = q >> 2, c = q & 3;
            cp16(dst0 + MATB_A2 + row * PRB + c * 16,
                 srcB + (size_t)kc * BLKB + (size_t)q * 16);
        }
        asm volatile("cp.async.commit_group;" ::: "memory");
    };

    float acc[4][4][4];
    #pragma unroll
    for (int i = 0; i < 4; i++)
        #pragma unroll
        for (int j = 0; j < 4; j++)
            #pragma unroll
            for (int q = 0; q < 4; q++) acc[i][j][q] = 0.f;

    int wm = (wid >> 2) * 64, wn = (wid & 3) * 32;   // 4x4 warp grid, 64x32 each
    uint32_t aoff = (uint32_t)(wm + (lane & 15)) * PRB + ((lane >> 4) << 4);
    uint32_t boff = (uint32_t)(wn + (lane & 7)) * PRB + ((lane & 8) << 1);

    #pragma unroll
    for (int s = 0; s < NSP_H - 1; s++) copy_stage(s, s);

    for (int kc = 0; kc < NKC; kc++) {
        wait_group<NSP_H - 2>();
        __syncthreads();
        int pf = kc + NSP_H - 1;
        if (pf < NKC) copy_stage(pf % NSP_H, pf);
        else asm volatile("cp.async.commit_group;" ::: "memory");

        uint32_t stA = smbase + (kc % NSP_H) * STGB2;
        uint32_t aA = stA + aoff;
        uint32_t aB = stA + MATB_A2 + boff;

        #pragma unroll
        for (int kk = 0; kk < 2; kk++) {
            uint32_t kb = kk * 32;
            uint32_t ah[4][4], bh[4][2];
            #pragma unroll
            for (int fm = 0; fm < 4; fm++)
                ldsm4(aA + fm * (16 * PRB) + kb, ah[fm]);
            #pragma unroll
            for (int fn = 0; fn < 4; fn++)
                ldsm2(aB + fn * (8 * PRB) + kb, bh[fn]);
            #pragma unroll
            for (int fm = 0; fm < 4; fm++)
                #pragma unroll
                for (int fn = 0; fn < 4; fn++)
                    MMA_F16(acc[fm][fn], ah[fm], bh[fn]);
        }
    }

    // --- epilogue -----------------------------------------------------------
    int g = lane >> 2, tig = lane & 3;
    int orow0 = mtile * 256 + wm + g;
    int ocol0 = ntile * HTN + wn + tig * 2;
    #pragma unroll
    for (int fn = 0; fn < 4; fn++) {
        int c = ocol0 + fn * 8;
        float b0 = bias[c], b1 = bias[c + 1];
        #pragma unroll
        for (int fm = 0; fm < 4; fm++) {
            int r = orow0 + fm * 16;
            *(float2*)(C + (size_t)r * VV + c) =
                make_float2(acc[fm][fn][0] + b0, acc[fm][fn][1] + b1);
            *(float2*)(C + (size_t)(r + 8) * VV + c) =
                make_float2(acc[fm][fn][2] + b0, acc[fm][fn][3] + b1);
        }
    }
}

// ---------------- launch ----------------------------------------------------
extern "C" void kernel_launch(void* const* d_in, const int* in_sizes, int n_in,
                              void* d_out, int out_size) {
    const int*   tokens        = (const int*)  d_in[0];
    const float* embed         = (const float*)d_in[1];
    const float* ln_scale      = (const float*)d_in[2];
    const float* ln_bias       = (const float*)d_in[3];
    const float* phase_W       = (const float*)d_in[4];
    const float* phase_b       = (const float*)d_in[5];
    const float* amp_W         = (const float*)d_in[6];
    const float* amp_b         = (const float*)d_in[7];
    const float* value_W       = (const float*)d_in[8];
    const float* value_b       = (const float*)d_in[9];
    const float* out_ln_scale  = (const float*)d_in[10];
    const float* out_ln_bias   = (const float*)d_in[11];
    const float* out_W         = (const float*)d_in[12];
    const float* out_b         = (const float*)d_in[13];
    const float* normout_scale = (const float*)d_in[14];
    const float* normout_bias  = (const float*)d_in[15];
    const float* head_W        = (const float*)d_in[16];
    const float* head_b        = (const float*)d_in[17];
    float* out = (float*)d_out;

    float *h, *hn, *val, *coef;
    unsigned char *whi, *ahi, *lwhi;
    cudaGetSymbolAddress((void**)&h,    g_h);
    cudaGetSymbolAddress((void**)&hn,   g_hn);
    cudaGetSymbolAddress((void**)&val,  g_val);
    cudaGetSymbolAddress((void**)&coef, g_coef);
    cudaGetSymbolAddress((void**)&whi,  g_Whi);
    cudaGetSymbolAddress((void**)&ahi,  g_Ahi);
    cudaGetSymbolAddress((void**)&lwhi, g_LWhi);

    cudaFuncSetAttribute(k_mm<true >, cudaFuncAttributeMaxDynamicSharedMemorySize, SMEM_L);
    cudaFuncSetAttribute(k_mm<false>, cudaFuncAttributeMaxDynamicSharedMemorySize, SMEM_L);
    cudaFuncSetAttribute(k_head,      cudaFuncAttributeMaxDynamicSharedMemorySize, SMEM_H2);
    cudaFuncSetAttribute(k_scanln,    cudaFuncAttributeMaxDynamicSharedMemorySize, SMEM_SCAN);

    k_convL<<<dim3(LNT, NKC, 2 * NLAYER), 256>>>(value_W, out_W, lwhi);

    dim3 mmLayer(HMT, LNT);
    size_t lwstep = (size_t)DD * DD * 2;

    for (int i = 0; i < NLAYER; i++) {
        // y2 = h + LN(h) into hn; split operand; fused coef.
        if (i == 0)
            k_ln<true, true, true><<<TOK / 16, 512>>>(
                nullptr, tokens, embed, ln_scale, ln_bias, hn, ahi,
                phase_W, phase_b, amp_W, amp_b);
        else
            k_ln<true, true, false><<<TOK / 16, 512>>>(
                h, nullptr, nullptr, ln_scale + i * DD, ln_bias + i * DD, hn, ahi,
                phase_W + (size_t)i * DD * PP, phase_b + i * PP,
                amp_W + (size_t)i * DD * PP, amp_b + i * PP);
        // val = (hn @ vW + vb) * coef, 64-token chunk sums fused
        k_mm<true><<<mmLayer, 512, SMEM_L>>>(
            ahi, lwhi + (2*i+0)*lwstep,
            value_b + i * DD, coef, nullptr, val, DD);
        // fused scan + out-LN + split operand
        k_scanln<<<NCHG, 512, SMEM_SCAN>>>(
            out_ln_scale + i * DD, out_ln_bias + i * DD, ahi);
        // h = y2 + sn @ oW + ob
        k_mm<false><<<mmLayer, 512, SMEM_L>>>(
            ahi, lwhi + (2*i+1)*lwstep,
            out_b + i * DD, nullptr, hn, h, DD);
    }

    // head weight conversion placed late: g_Whi stays L2-warm for k_head
    k_convB<<<dim3(HNT, NKC), 256>>>(head_W, VV, whi);
    // final: split(LN(h)); head GEMM with 256-row tiles
    k_ln<false, false, false><<<TOK / 16, 512>>>(
        h, nullptr, nullptr, normout_scale, normout_bias,
        nullptr, ahi, nullptr, nullptr, nullptr, nullptr);
    k_head<<<dim3(TOK / 256, HNT), 512, SMEM_H2>>>(ahi, whi, head_b, out);
}